// round 9
// baseline (speedup 1.0000x reference)
#include <cuda_runtime.h>
#include <cuda_bf16.h>
#include <cstdint>

#define D_IN 1024
#define H_SZ 64
#define M_TOT 8192   // B*T
#define T_SEQ 2048
#define B_SZ 4
#define NSPLIT 4
#define TILES_PER_SPLIT 8
#define QTILES 32            // T_SEQ / 64

// ---------------- global scratch ----------------
__device__ __nv_bfloat16 g_wh[192 * D_IN];     // [w*64+n][k]  (W transposed)
__device__ __nv_bfloat16 g_wl[192 * D_IN];
__device__ __nv_bfloat16 g_qh[M_TOT * H_SZ];   // [global token][h]
__device__ __nv_bfloat16 g_ql[M_TOT * H_SZ];
__device__ __nv_bfloat16 g_kh[M_TOT * H_SZ];
__device__ __nv_bfloat16 g_kl[M_TOT * H_SZ];
__device__ __nv_bfloat16 g_vth[B_SZ][H_SZ][T_SEQ];  // V transposed per batch
__device__ __nv_bfloat16 g_vtl[B_SZ][H_SZ][T_SEQ];
// split-KV partials
__device__ float g_po[NSPLIT][M_TOT][H_SZ];    // unnormalized O
__device__ float g_pm[NSPLIT][M_TOT];          // running max (log2 domain)
__device__ float g_pl[NSPLIT][M_TOT];          // running sum

// ---------------- helpers ----------------
__device__ __forceinline__ void mma_bf16(float d[4], const uint32_t a[4],
                                         const uint32_t b[2]) {
    asm("mma.sync.aligned.m16n8k16.row.col.f32.bf16.bf16.f32 "
        "{%0,%1,%2,%3}, {%4,%5,%6,%7}, {%8,%9}, {%0,%1,%2,%3};\n"
        : "+f"(d[0]), "+f"(d[1]), "+f"(d[2]), "+f"(d[3])
        : "r"(a[0]), "r"(a[1]), "r"(a[2]), "r"(a[3]), "r"(b[0]), "r"(b[1]));
}

__device__ __forceinline__ uint32_t pack2bf(float v0, float v1) {
    unsigned short l = __bfloat16_as_ushort(__float2bfloat16(v0));
    unsigned short h = __bfloat16_as_ushort(__float2bfloat16(v1));
    return (uint32_t)l | ((uint32_t)h << 16);
}

__device__ __forceinline__ void split_pair(float x, float y,
                                           uint32_t& hi, uint32_t& lo) {
    __nv_bfloat16 hx = __float2bfloat16(x);
    __nv_bfloat16 hy = __float2bfloat16(y);
    hi = (uint32_t)__bfloat16_as_ushort(hx) |
         ((uint32_t)__bfloat16_as_ushort(hy) << 16);
    lo = pack2bf(x - __bfloat162float(hx), y - __bfloat162float(hy));
}

// degree-6 Taylor of 2^x (rel err ~2e-5), FMA pipe only, no MUFU.
__device__ __forceinline__ float exp2_poly(float x) {
    x = fmaxf(x, -126.0f);
    float fl = floorf(x);
    float f  = x - fl;
    float p = 1.5403530e-4f;
    p = fmaf(p, f, 1.3333558e-3f);
    p = fmaf(p, f, 9.6181291e-3f);
    p = fmaf(p, f, 5.5504109e-2f);
    p = fmaf(p, f, 2.4022651e-1f);
    p = fmaf(p, f, 6.9314718e-1f);
    p = fmaf(p, f, 1.0f);
    int e = (int)fl;
    return __int_as_float((e + 127) << 23) * p;
}

#define CP_ASYNC16(dst, src) \
    asm volatile("cp.async.cg.shared.global [%0], [%1], 16;" \
                 :: "r"(dst), "l"(src) : "memory")
#define CP_COMMIT() asm volatile("cp.async.commit_group;" ::: "memory")
#define CP_WAIT1()  asm volatile("cp.async.wait_group 1;" ::: "memory")
#define CP_WAIT0()  asm volatile("cp.async.wait_group 0;" ::: "memory")

// ---------------------------------------------------------------------------
// transpose + split W: [k][n] fp32 -> [w*64+n][k] bf16 hi/lo
// ---------------------------------------------------------------------------
__global__ __launch_bounds__(256) void split_w_kernel(
    const float* __restrict__ Wq, const float* __restrict__ Wk,
    const float* __restrict__ Wv)
{
    const int idx = blockIdx.x * 256 + threadIdx.x;
    const int w = idx >> 16;
    const int n = (idx >> 10) & 63;
    const int k = idx & 1023;
    const float* W = (w == 0) ? Wq : ((w == 1) ? Wk : Wv);
    const float val = W[k * 64 + n];
    __nv_bfloat16 h = __float2bfloat16(val);
    g_wh[idx] = h;
    g_wl[idx] = __float2bfloat16(val - __bfloat162float(h));
}

// ---------------------------------------------------------------------------
// QKV projection via mma.sync bf16 (3-term split), cp.async double-buffered.
// 256 threads, tile M=64, N=192, K chunks of 32. 128 CTAs, 1 sync/chunk.
// x streams as raw fp32; hi/lo split happens at fragment-extraction time.
// Stage layout: [xs fp32 64x40 | ws_h bf16 192x40 | ws_l bf16 192x40] = 40960B.
// ---------------------------------------------------------------------------
#define QS_STAGE 40960
#define QS_WH    10240
#define QS_WL    25600

__global__ __launch_bounds__(256) void qkv_mma_kernel(const float* __restrict__ x)
{
    extern __shared__ __align__(16) char qsm[];
    const uint32_t smbase = (uint32_t)__cvta_generic_to_shared(qsm);

    const int tid  = threadIdx.x;
    const int lane = tid & 31;
    const int wid  = tid >> 5;
    const int wm = wid & 1, wn = wid >> 1;
    const int lq = lane >> 2;
    const int lc = (lane & 3) * 2;
    const int m0 = blockIdx.x * 64;

    #define QPREF(stage, c_)                                                   \
    do {                                                                       \
        const uint32_t st = smbase + (stage) * QS_STAGE;                       \
        const int k0 = (c_) * 32;                                              \
        _Pragma("unroll")                                                      \
        for (int p = 0; p < 2; p++) {                                          \
            const int idx = tid + p * 256;                                     \
            const int r = idx >> 3, u = idx & 7;                               \
            CP_ASYNC16(st + r * 160 + u * 16,                                  \
                       &x[(m0 + r) * D_IN + k0 + u * 4]);                      \
        }                                                                      \
        _Pragma("unroll")                                                      \
        for (int p = 0; p < 3; p++) {                                          \
            const int idx = tid + p * 256;                                     \
            const int r = idx >> 2, u = idx & 3;                               \
            CP_ASYNC16(st + QS_WH + r * 80 + u * 16,                           \
                       &g_wh[r * D_IN + k0 + u * 8]);                          \
            CP_ASYNC16(st + QS_WL + r * 80 + u * 16,                           \
                       &g_wl[r * D_IN + k0 + u * 8]);                          \
        }                                                                      \
    } while (0)

    float d[2][6][4];
    #pragma unroll
    for (int mf = 0; mf < 2; mf++)
        #pragma unroll
        for (int j = 0; j < 6; j++)
            #pragma unroll
            for (int r = 0; r < 4; r++) d[mf][j][r] = 0.0f;

    QPREF(0, 0);
    CP_COMMIT();

    for (int c = 0; c < 32; c++) {
        const int buf = c & 1;
        const bool more = (c + 1 < 32);
        if (more) CP_WAIT1(); else CP_WAIT0();
        __syncthreads();
        // prefetch next chunk into the other stage (safe: that stage's compute
        // finished before this barrier)
        if (more) { QPREF(buf ^ 1, c + 1); CP_COMMIT(); }

        const float* xs = (const float*)(qsm + buf * QS_STAGE);
        const __nv_bfloat16* wsh = (const __nv_bfloat16*)(qsm + buf * QS_STAGE + QS_WH);
        const __nv_bfloat16* wsl = (const __nv_bfloat16*)(qsm + buf * QS_STAGE + QS_WL);

        #pragma unroll
        for (int kc = 0; kc < 2; kc++) {
            const int cb = kc * 16 + lc;
            uint32_t ah[2][4], al[2][4];
            #pragma unroll
            for (int mf = 0; mf < 2; mf++) {
                const int r0 = wm * 32 + mf * 16 + lq;
                float2 a0 = *(const float2*)&xs[r0 * 40 + cb];
                float2 a1 = *(const float2*)&xs[(r0 + 8) * 40 + cb];
                float2 a2 = *(const float2*)&xs[r0 * 40 + cb + 8];
                float2 a3 = *(const float2*)&xs[(r0 + 8) * 40 + cb + 8];
                split_pair(a0.x, a0.y, ah[mf][0], al[mf][0]);
                split_pair(a1.x, a1.y, ah[mf][1], al[mf][1]);
                split_pair(a2.x, a2.y, ah[mf][2], al[mf][2]);
                split_pair(a3.x, a3.y, ah[mf][3], al[mf][3]);
            }
            #pragma unroll
            for (int j = 0; j < 6; j++) {
                const int wr = wn * 48 + j * 8 + lq;
                uint32_t bh[2], bl[2];
                bh[0] = *(const uint32_t*)&wsh[wr * 40 + cb];
                bh[1] = *(const uint32_t*)&wsh[wr * 40 + cb + 8];
                bl[0] = *(const uint32_t*)&wsl[wr * 40 + cb];
                bl[1] = *(const uint32_t*)&wsl[wr * 40 + cb + 8];
                #pragma unroll
                for (int mf = 0; mf < 2; mf++) {
                    mma_bf16(d[mf][j], ah[mf], bh);
                    mma_bf16(d[mf][j], ah[mf], bl);
                    mma_bf16(d[mf][j], al[mf], bh);
                }
            }
        }
    }

    // epilogue: hi/lo split + store
    #pragma unroll
    for (int mf = 0; mf < 2; mf++) {
        #pragma unroll
        for (int j = 0; j < 6; j++) {
            const int col = wn * 48 + j * 8 + lc;
            const int mat = col >> 6;
            const int h   = col & 63;
            #pragma unroll
            for (int half = 0; half < 2; half++) {
                const int row = m0 + wm * 32 + mf * 16 + lq + half * 8;
                const float v0 = d[mf][j][half * 2 + 0];
                const float v1 = d[mf][j][half * 2 + 1];
                uint32_t hi, lo;
                split_pair(v0, v1, hi, lo);
                if (mat == 0) {
                    *(uint32_t*)&g_qh[row * 64 + h] = hi;
                    *(uint32_t*)&g_ql[row * 64 + h] = lo;
                } else if (mat == 1) {
                    *(uint32_t*)&g_kh[row * 64 + h] = hi;
                    *(uint32_t*)&g_kl[row * 64 + h] = lo;
                } else {
                    const int b = row >> 11, t = row & 2047;
                    __nv_bfloat16 h0 = __float2bfloat16(v0);
                    __nv_bfloat16 h1 = __float2bfloat16(v1);
                    g_vth[b][h][t]     = h0;
                    g_vth[b][h + 1][t] = h1;
                    g_vtl[b][h][t]     = __float2bfloat16(v0 - __bfloat162float(h0));
                    g_vtl[b][h + 1][t] = __float2bfloat16(v1 - __bfloat162float(h1));
                }
            }
        }
    }
}

// ---------------------------------------------------------------------------
// FA2-style split-KV flash attention (R8, kept). BQ=64, 128 threads, 4 warps.
// ---------------------------------------------------------------------------
#define SCALE_L2E 0.18033688f   // 64^-0.5 * log2(e)
#define STAGE_BYTES 36864
#define ARR_BYTES   9216        // 64*72*2

__global__ __launch_bounds__(128, 3) void attn_kernel()
{
    const int qt = (QTILES - 1) - blockIdx.x;   // longest-first
    const int ntile = qt + 1;
    const int sp = blockIdx.z;
    const int t0 = sp * TILES_PER_SPLIT;
    if (t0 >= ntile) return;
    const int t1 = min(t0 + TILES_PER_SPLIT, ntile);

    extern __shared__ __align__(16) char smbuf[];
    const uint32_t smbase = (uint32_t)__cvta_generic_to_shared(smbuf);

    const int tid  = threadIdx.x;
    const int lane = tid & 31;
    const int warp = tid >> 5;
    const int lq = lane >> 2;
    const int lc = (lane & 3) * 2;

    const int b  = blockIdx.y;
    const int q_base = qt * 64;
    const int boff = b * T_SEQ * 64;
    const __nv_bfloat16* qbh = g_qh + boff;
    const __nv_bfloat16* qbl = g_ql + boff;
    const __nv_bfloat16* kbh = g_kh + boff;
    const __nv_bfloat16* kbl = g_kl + boff;

    {
        __nv_bfloat16* Qh = (__nv_bfloat16*)(smbuf);
        __nv_bfloat16* Ql = (__nv_bfloat16*)(smbuf + ARR_BYTES);
        #pragma unroll
        for (int p = 0; p < 4; p++) {
            const int idx = tid + p * 128;
            const int r = idx >> 3, u = idx & 7;
            *(uint4*)&Qh[r * 72 + u * 8] =
                *(const uint4*)&qbh[(q_base + r) * 64 + u * 8];
            *(uint4*)&Ql[r * 72 + u * 8] =
                *(const uint4*)&qbl[(q_base + r) * 64 + u * 8];
        }
    }
    __syncthreads();
    uint32_t qa_h[4][4], qa_l[4][4];
    {
        const __nv_bfloat16* Qh = (const __nv_bfloat16*)(smbuf);
        const __nv_bfloat16* Ql = (const __nv_bfloat16*)(smbuf + ARR_BYTES);
        const int rb = warp * 16;
        #pragma unroll
        for (int kc = 0; kc < 4; kc++) {
            const int cb = kc * 16 + lc;
            qa_h[kc][0] = *(const uint32_t*)&Qh[(rb + lq) * 72 + cb];
            qa_h[kc][1] = *(const uint32_t*)&Qh[(rb + lq + 8) * 72 + cb];
            qa_h[kc][2] = *(const uint32_t*)&Qh[(rb + lq) * 72 + cb + 8];
            qa_h[kc][3] = *(const uint32_t*)&Qh[(rb + lq + 8) * 72 + cb + 8];
            qa_l[kc][0] = *(const uint32_t*)&Ql[(rb + lq) * 72 + cb];
            qa_l[kc][1] = *(const uint32_t*)&Ql[(rb + lq + 8) * 72 + cb];
            qa_l[kc][2] = *(const uint32_t*)&Ql[(rb + lq) * 72 + cb + 8];
            qa_l[kc][3] = *(const uint32_t*)&Ql[(rb + lq + 8) * 72 + cb + 8];
        }
    }
    __syncthreads();

    #define PREFETCH(stage, kb_)                                                 \
    do {                                                                         \
        const uint32_t stoff = smbase + (stage) * STAGE_BYTES;                   \
        _Pragma("unroll")                                                        \
        for (int p = 0; p < 4; p++) {                                            \
            const int idx = tid + p * 128;                                       \
            const int r = idx >> 3, u = idx & 7;                                 \
            const uint32_t o = stoff + r * 144 + u * 16;                         \
            CP_ASYNC16(o,                  &kbh[((kb_) + r) * 64 + u * 8]);      \
            CP_ASYNC16(o + ARR_BYTES,      &kbl[((kb_) + r) * 64 + u * 8]);      \
            CP_ASYNC16(o + 2 * ARR_BYTES,  &g_vth[b][r][(kb_) + u * 8]);         \
            CP_ASYNC16(o + 3 * ARR_BYTES,  &g_vtl[b][r][(kb_) + u * 8]);         \
        }                                                                        \
    } while (0)

    PREFETCH(0, t0 * 64);
    CP_COMMIT();

    float of[8][4];
    #pragma unroll
    for (int j = 0; j < 8; j++)
        #pragma unroll
        for (int r = 0; r < 4; r++) of[j][r] = 0.0f;
    float m2[2] = {-1e30f, -1e30f};
    float lsum[2] = {0.0f, 0.0f};

    int buf = 0;
    for (int t = t0; t < t1; t++) {
        const int kb = t * 64;
        const bool more = (t + 1 < t1);
        if (more) { PREFETCH(buf ^ 1, (t + 1) * 64); CP_COMMIT(); }
        if (more) CP_WAIT1(); else CP_WAIT0();
        __syncthreads();

        const __nv_bfloat16* Kh = (const __nv_bfloat16*)(smbuf + buf * STAGE_BYTES);
        const __nv_bfloat16* Kl = Kh + ARR_BYTES / 2;
        const __nv_bfloat16* Vh = Kh + ARR_BYTES;
        const __nv_bfloat16* Vl = Kh + 3 * ARR_BYTES / 2;

        float s[8][4];
        #pragma unroll
        for (int j = 0; j < 8; j++)
            #pragma unroll
            for (int r = 0; r < 4; r++) s[j][r] = 0.0f;
        #pragma unroll
        for (int kc = 0; kc < 4; kc++) {
            const int cb = kc * 16 + lc;
            #pragma unroll
            for (int j = 0; j < 8; j++) {
                const int sr = j * 8 + lq;
                uint32_t bh[2], bl[2];
                bh[0] = *(const uint32_t*)&Kh[sr * 72 + cb];
                bh[1] = *(const uint32_t*)&Kh[sr * 72 + cb + 8];
                bl[0] = *(const uint32_t*)&Kl[sr * 72 + cb];
                bl[1] = *(const uint32_t*)&Kl[sr * 72 + cb + 8];
                mma_bf16(s[j], qa_h[kc], bh);
                mma_bf16(s[j], qa_h[kc], bl);
                mma_bf16(s[j], qa_l[kc], bh);
            }
        }

        if (t == qt) {
            #pragma unroll
            for (int j = 0; j < 8; j++) {
                const int col = kb + j * 8 + lc;
                #pragma unroll
                for (int half = 0; half < 2; half++) {
                    const int qrow = q_base + warp * 16 + lq + half * 8;
                    s[j][half * 2 + 0] = (col     <= qrow) ? s[j][half * 2 + 0] * SCALE_L2E : -1e30f;
                    s[j][half * 2 + 1] = (col + 1 <= qrow) ? s[j][half * 2 + 1] * SCALE_L2E : -1e30f;
                }
            }
        } else {
            #pragma unroll
            for (int j = 0; j < 8; j++)
                #pragma unroll
                for (int r = 0; r < 4; r++) s[j][r] *= SCALE_L2E;
        }

        float pm[2] = {-1e30f, -1e30f};
        #pragma unroll
        for (int j = 0; j < 8; j++) {
            pm[0] = fmaxf(pm[0], fmaxf(s[j][0], s[j][1]));
            pm[1] = fmaxf(pm[1], fmaxf(s[j][2], s[j][3]));
        }
        pm[0] = fmaxf(pm[0], __shfl_xor_sync(0xffffffffu, pm[0], 1));
        pm[1] = fmaxf(pm[1], __shfl_xor_sync(0xffffffffu, pm[1], 1));
        pm[0] = fmaxf(pm[0], __shfl_xor_sync(0xffffffffu, pm[0], 2));
        pm[1] = fmaxf(pm[1], __shfl_xor_sync(0xffffffffu, pm[1], 2));

        float mnew[2], alpha[2];
        #pragma unroll
        for (int half = 0; half < 2; half++) {
            mnew[half]  = fmaxf(m2[half], pm[half]);
            alpha[half] = exp2_poly(m2[half] - mnew[half]);
            m2[half]    = mnew[half];
        }
        float ps[2] = {0.0f, 0.0f};
        #pragma unroll
        for (int j = 0; j < 8; j++) {
            s[j][0] = exp2_poly(s[j][0] - mnew[0]);
            s[j][1] = exp2_poly(s[j][1] - mnew[0]);
            s[j][2] = exp2_poly(s[j][2] - mnew[1]);
            s[j][3] = exp2_poly(s[j][3] - mnew[1]);
            ps[0] += s[j][0] + s[j][1];
            ps[1] += s[j][2] + s[j][3];
        }
        ps[0] += __shfl_xor_sync(0xffffffffu, ps[0], 1);
        ps[1] += __shfl_xor_sync(0xffffffffu, ps[1], 1);
        ps[0] += __shfl_xor_sync(0xffffffffu, ps[0], 2);
        ps[1] += __shfl_xor_sync(0xffffffffu, ps[1], 2);

        lsum[0] = lsum[0] * alpha[0] + ps[0];
        lsum[1] = lsum[1] * alpha[1] + ps[1];
        #pragma unroll
        for (int j = 0; j < 8; j++) {
            of[j][0] *= alpha[0]; of[j][1] *= alpha[0];
            of[j][2] *= alpha[1]; of[j][3] *= alpha[1];
        }

        #pragma unroll
        for (int kc = 0; kc < 4; kc++) {
            const int cb = kc * 16 + lc;
            uint32_t ap_h[4], ap_l[4];
            split_pair(s[2 * kc][0],     s[2 * kc][1],     ap_h[0], ap_l[0]);
            split_pair(s[2 * kc][2],     s[2 * kc][3],     ap_h[1], ap_l[1]);
            split_pair(s[2 * kc + 1][0], s[2 * kc + 1][1], ap_h[2], ap_l[2]);
            split_pair(s[2 * kc + 1][2], s[2 * kc + 1][3], ap_h[3], ap_l[3]);
            #pragma unroll
            for (int j = 0; j < 8; j++) {
                const int hr = j * 8 + lq;
                uint32_t bh[2], bl[2];
                bh[0] = *(const uint32_t*)&Vh[hr * 72 + cb];
                bh[1] = *(const uint32_t*)&Vh[hr * 72 + cb + 8];
                bl[0] = *(const uint32_t*)&Vl[hr * 72 + cb];
                bl[1] = *(const uint32_t*)&Vl[hr * 72 + cb + 8];
                mma_bf16(of[j], ap_h, bh);
                mma_bf16(of[j], ap_h, bl);
                mma_bf16(of[j], ap_l, bh);
            }
        }
        __syncthreads();
        buf ^= 1;
    }

    const int rowg = b * T_SEQ + q_base + warp * 16 + lq;
    #pragma unroll
    for (int j = 0; j < 8; j++) {
        const int col = j * 8 + lc;
        *(float2*)&g_po[sp][rowg][col]     = make_float2(of[j][0], of[j][1]);
        *(float2*)&g_po[sp][rowg + 8][col] = make_float2(of[j][2], of[j][3]);
    }
    if ((lane & 3) == 0) {
        g_pm[sp][rowg]     = m2[0];
        g_pm[sp][rowg + 8] = m2[1];
        g_pl[sp][rowg]     = lsum[0];
        g_pl[sp][rowg + 8] = lsum[1];
    }
}

// ---------------------------------------------------------------------------
// Combine partial splits, float4 per thread, batched split loads.
// grid 1024 x 128 threads: thread -> (row, 4 cols).
// ---------------------------------------------------------------------------
__global__ __launch_bounds__(128) void combine_kernel(float* __restrict__ out)
{
    const int idx = blockIdx.x * 128 + threadIdx.x;
    const int r = idx >> 4;
    const int c = (idx & 15) * 4;
    const int rr = r & (T_SEQ - 1);
    const int qt = rr >> 6;
    const int nsplit = ((qt + 1) + TILES_PER_SPLIT - 1) / TILES_PER_SPLIT;

    float pm[NSPLIT];
    float M = -1e30f;
    #pragma unroll
    for (int s = 0; s < NSPLIT; s++) {
        pm[s] = (s < nsplit) ? g_pm[s][r] : -1e30f;
        M = fmaxf(M, pm[s]);
    }
    float L = 0.0f;
    float4 acc = make_float4(0.0f, 0.0f, 0.0f, 0.0f);
    #pragma unroll
    for (int s = 0; s < NSPLIT; s++) {
        if (s < nsplit) {
            const float w = exp2_poly(pm[s] - M);
            L += w * g_pl[s][r];
            float4 o = *(const float4*)&g_po[s][r][c];
            acc.x += w * o.x; acc.y += w * o.y;
            acc.z += w * o.z; acc.w += w * o.w;
        }
    }
    const float inv = 1.0f / L;
    acc.x *= inv; acc.y *= inv; acc.z *= inv; acc.w *= inv;
    *(float4*)&out[r * 64 + c] = acc;
}

extern "C" void kernel_launch(void* const* d_in, const int* in_sizes, int n_in,
                              void* d_out, int out_size)
{
    const float* x  = (const float*)d_in[0];
    const float* Wq = (const float*)d_in[1];
    const float* Wk = (const float*)d_in[2];
    const float* Wv = (const float*)d_in[3];
    float* out = (float*)d_out;

    cudaFuncSetAttribute(attn_kernel,
                         cudaFuncAttributeMaxDynamicSharedMemorySize,
                         2 * STAGE_BYTES);
    cudaFuncSetAttribute(qkv_mma_kernel,
                         cudaFuncAttributeMaxDynamicSharedMemorySize,
                         2 * QS_STAGE);

    split_w_kernel<<<3 * 64 * 1024 / 256, 256>>>(Wq, Wk, Wv);
    qkv_mma_kernel<<<M_TOT / 64, 256, 2 * QS_STAGE>>>(x);
    attn_kernel<<<dim3(QTILES, B_SZ, NSPLIT), 128, 2 * STAGE_BYTES>>>();
    combine_kernel<<<M_TOT * H_SZ / 512, 128>>>(out);
}

// round 10
// speedup vs baseline: 1.6182x; 1.6182x over previous
#include <cuda_runtime.h>
#include <cuda_bf16.h>
#include <cstdint>

#define D_IN 1024
#define H_SZ 64
#define M_TOT 8192   // B*T
#define T_SEQ 2048
#define B_SZ 4
#define NSPLIT 4
#define TILES_PER_SPLIT 8
#define QTILES 32            // T_SEQ / 64

// ---------------- global scratch ----------------
__device__ __nv_bfloat16 g_wh[192 * D_IN];     // [w*64+n][k]  (W transposed)
__device__ __nv_bfloat16 g_wl[192 * D_IN];
__device__ __nv_bfloat16 g_qh[M_TOT * H_SZ];   // [global token][h]
__device__ __nv_bfloat16 g_ql[M_TOT * H_SZ];
__device__ __nv_bfloat16 g_kh[M_TOT * H_SZ];
__device__ __nv_bfloat16 g_kl[M_TOT * H_SZ];
__device__ __nv_bfloat16 g_vth[B_SZ][H_SZ][T_SEQ];  // V transposed per batch
__device__ __nv_bfloat16 g_vtl[B_SZ][H_SZ][T_SEQ];
// split-KV partials
__device__ float g_po[NSPLIT][M_TOT][H_SZ];    // unnormalized O
__device__ float g_pm[NSPLIT][M_TOT];          // running max (log2 domain)
__device__ float g_pl[NSPLIT][M_TOT];          // running sum

// ---------------- helpers ----------------
__device__ __forceinline__ void mma_bf16(float d[4], const uint32_t a[4],
                                         const uint32_t b[2]) {
    asm("mma.sync.aligned.m16n8k16.row.col.f32.bf16.bf16.f32 "
        "{%0,%1,%2,%3}, {%4,%5,%6,%7}, {%8,%9}, {%0,%1,%2,%3};\n"
        : "+f"(d[0]), "+f"(d[1]), "+f"(d[2]), "+f"(d[3])
        : "r"(a[0]), "r"(a[1]), "r"(a[2]), "r"(a[3]), "r"(b[0]), "r"(b[1]));
}

__device__ __forceinline__ uint32_t pack2bf(float v0, float v1) {
    unsigned short l = __bfloat16_as_ushort(__float2bfloat16(v0));
    unsigned short h = __bfloat16_as_ushort(__float2bfloat16(v1));
    return (uint32_t)l | ((uint32_t)h << 16);
}

__device__ __forceinline__ void split_pair(float x, float y,
                                           uint32_t& hi, uint32_t& lo) {
    __nv_bfloat16 hx = __float2bfloat16(x);
    __nv_bfloat16 hy = __float2bfloat16(y);
    hi = (uint32_t)__bfloat16_as_ushort(hx) |
         ((uint32_t)__bfloat16_as_ushort(hy) << 16);
    lo = pack2bf(x - __bfloat162float(hx), y - __bfloat162float(hy));
}

// degree-6 Taylor of 2^x (rel err ~2e-5), FMA pipe only, no MUFU.
__device__ __forceinline__ float exp2_poly(float x) {
    x = fmaxf(x, -126.0f);
    float fl = floorf(x);
    float f  = x - fl;
    float p = 1.5403530e-4f;
    p = fmaf(p, f, 1.3333558e-3f);
    p = fmaf(p, f, 9.6181291e-3f);
    p = fmaf(p, f, 5.5504109e-2f);
    p = fmaf(p, f, 2.4022651e-1f);
    p = fmaf(p, f, 6.9314718e-1f);
    p = fmaf(p, f, 1.0f);
    int e = (int)fl;
    return __int_as_float((e + 127) << 23) * p;
}

#define CP_ASYNC16(dst, src) \
    asm volatile("cp.async.cg.shared.global [%0], [%1], 16;" \
                 :: "r"(dst), "l"(src) : "memory")
#define CP_COMMIT() asm volatile("cp.async.commit_group;" ::: "memory")
#define CP_WAIT1()  asm volatile("cp.async.wait_group 1;" ::: "memory")
#define CP_WAIT0()  asm volatile("cp.async.wait_group 0;" ::: "memory")

// ---------------------------------------------------------------------------
// transpose + split W: [k][n] fp32 -> [w*64+n][k] bf16 hi/lo
// ---------------------------------------------------------------------------
__global__ __launch_bounds__(256) void split_w_kernel(
    const float* __restrict__ Wq, const float* __restrict__ Wk,
    const float* __restrict__ Wv)
{
    const int idx = blockIdx.x * 256 + threadIdx.x;
    const int w = idx >> 16;
    const int n = (idx >> 10) & 63;
    const int k = idx & 1023;
    const float* W = (w == 0) ? Wq : ((w == 1) ? Wk : Wv);
    const float val = W[k * 64 + n];
    __nv_bfloat16 h = __float2bfloat16(val);
    g_wh[idx] = h;
    g_wl[idx] = __float2bfloat16(val - __bfloat162float(h));
}

// ---------------------------------------------------------------------------
// QKV projection via mma.sync bf16 (3-term split), software-pipelined:
//  - x fp32 loaded to REGISTERS one chunk ahead (LDG overlaps compute)
//  - x converted hi/lo ONCE per element at STS time (R8 semantics)
//  - W tiles streamed via cp.async into the double-buffered stage
//  - ONE __syncthreads per chunk
// 256 threads, tile M=64, N=192, K chunks of 32, 128 CTAs.
// Stage (bf16): xs_h[64][40] | xs_l[64][40] | ws_h[192][40] | ws_l[192][40]
// ---------------------------------------------------------------------------
#define QS_XL    5120
#define QS_WH    10240
#define QS_WL    25600
#define QS_STAGE 40960

__global__ __launch_bounds__(256) void qkv_mma_kernel(const float* __restrict__ x)
{
    extern __shared__ __align__(16) char qsm[];
    const uint32_t smbase = (uint32_t)__cvta_generic_to_shared(qsm);

    const int tid  = threadIdx.x;
    const int lane = tid & 31;
    const int wid  = tid >> 5;
    const int wm = wid & 1, wn = wid >> 1;
    const int lq = lane >> 2;
    const int lc = (lane & 3) * 2;
    const int m0 = blockIdx.x * 64;

    // x-staging assignment: thread covers rows xr0/xr1, 16-byte group xu
    const int xr0 = tid >> 3;            // 0..31
    const int xr1 = xr0 + 32;            // 32..63
    const int xu  = tid & 7;             // 0..7 (xu*4 floats)

    #define QPREF_W(stage, c_)                                                 \
    do {                                                                       \
        const uint32_t st = smbase + (stage) * QS_STAGE;                       \
        const int k0 = (c_) * 32;                                              \
        _Pragma("unroll")                                                      \
        for (int p = 0; p < 3; p++) {                                          \
            const int idx = tid + p * 256;                                     \
            const int r = idx >> 2, u = idx & 3;                               \
            CP_ASYNC16(st + QS_WH + r * 80 + u * 16,                           \
                       &g_wh[r * D_IN + k0 + u * 8]);                          \
            CP_ASYNC16(st + QS_WL + r * 80 + u * 16,                           \
                       &g_wl[r * D_IN + k0 + u * 8]);                          \
        }                                                                      \
    } while (0)

    float d[2][6][4];
    #pragma unroll
    for (int mf = 0; mf < 2; mf++)
        #pragma unroll
        for (int j = 0; j < 6; j++)
            #pragma unroll
            for (int r = 0; r < 4; r++) d[mf][j][r] = 0.0f;

    // prologue: x(0) -> regs, W(0) -> stage 0
    float4 xr[2];
    xr[0] = *(const float4*)&x[(m0 + xr0) * D_IN + xu * 4];
    xr[1] = *(const float4*)&x[(m0 + xr1) * D_IN + xu * 4];
    QPREF_W(0, 0);
    CP_COMMIT();

    for (int c = 0; c < 32; c++) {
        const int buf = c & 1;
        char* st = qsm + buf * QS_STAGE;
        __nv_bfloat16* xs_h = (__nv_bfloat16*)st;
        __nv_bfloat16* xs_l = (__nv_bfloat16*)(st + QS_XL);
        const __nv_bfloat16* wsh = (const __nv_bfloat16*)(st + QS_WH);
        const __nv_bfloat16* wsl = (const __nv_bfloat16*)(st + QS_WL);

        // (a) convert x(c) regs -> STS (stage buf free since chunk c-2)
        #pragma unroll
        for (int p = 0; p < 2; p++) {
            const int r = (p == 0) ? xr0 : xr1;
            uint32_t hi01, lo01, hi23, lo23;
            split_pair(xr[p].x, xr[p].y, hi01, lo01);
            split_pair(xr[p].z, xr[p].w, hi23, lo23);
            *(uint2*)&xs_h[r * 40 + xu * 4] = make_uint2(hi01, hi23);
            *(uint2*)&xs_l[r * 40 + xu * 4] = make_uint2(lo01, lo23);
        }
        // (b) LDG x(c+1) -> regs (latency hidden behind this chunk's MMAs)
        if (c + 1 < 32) {
            const int k0n = (c + 1) * 32;
            xr[0] = *(const float4*)&x[(m0 + xr0) * D_IN + k0n + xu * 4];
            xr[1] = *(const float4*)&x[(m0 + xr1) * D_IN + k0n + xu * 4];
        }
        // (c) wait W(c), barrier (x(c) STS visible; stage buf^1 compute done)
        CP_WAIT0();
        __syncthreads();
        // (d) prefetch W(c+1) into stage buf^1 (its chunk c-1 compute is done)
        if (c + 1 < 32) { QPREF_W(buf ^ 1, c + 1); CP_COMMIT(); }

        // (e) compute chunk c
        #pragma unroll
        for (int kc = 0; kc < 2; kc++) {
            const int cb = kc * 16 + lc;
            uint32_t ah[2][4], al[2][4];
            #pragma unroll
            for (int mf = 0; mf < 2; mf++) {
                const int rb = wm * 32 + mf * 16;
                ah[mf][0] = *(const uint32_t*)&xs_h[(rb + lq) * 40 + cb];
                ah[mf][1] = *(const uint32_t*)&xs_h[(rb + lq + 8) * 40 + cb];
                ah[mf][2] = *(const uint32_t*)&xs_h[(rb + lq) * 40 + cb + 8];
                ah[mf][3] = *(const uint32_t*)&xs_h[(rb + lq + 8) * 40 + cb + 8];
                al[mf][0] = *(const uint32_t*)&xs_l[(rb + lq) * 40 + cb];
                al[mf][1] = *(const uint32_t*)&xs_l[(rb + lq + 8) * 40 + cb];
                al[mf][2] = *(const uint32_t*)&xs_l[(rb + lq) * 40 + cb + 8];
                al[mf][3] = *(const uint32_t*)&xs_l[(rb + lq + 8) * 40 + cb + 8];
            }
            #pragma unroll
            for (int j = 0; j < 6; j++) {
                const int wr = wn * 48 + j * 8 + lq;
                uint32_t bh[2], bl[2];
                bh[0] = *(const uint32_t*)&wsh[wr * 40 + cb];
                bh[1] = *(const uint32_t*)&wsh[wr * 40 + cb + 8];
                bl[0] = *(const uint32_t*)&wsl[wr * 40 + cb];
                bl[1] = *(const uint32_t*)&wsl[wr * 40 + cb + 8];
                #pragma unroll
                for (int mf = 0; mf < 2; mf++) {
                    mma_bf16(d[mf][j], ah[mf], bh);
                    mma_bf16(d[mf][j], ah[mf], bl);
                    mma_bf16(d[mf][j], al[mf], bh);
                }
            }
        }
        __syncthreads();   // stage buf reusable for chunk c+2's STS
    }

    // epilogue: hi/lo split + store
    #pragma unroll
    for (int mf = 0; mf < 2; mf++) {
        #pragma unroll
        for (int j = 0; j < 6; j++) {
            const int col = wn * 48 + j * 8 + lc;
            const int mat = col >> 6;
            const int h   = col & 63;
            #pragma unroll
            for (int half = 0; half < 2; half++) {
                const int row = m0 + wm * 32 + mf * 16 + lq + half * 8;
                const float v0 = d[mf][j][half * 2 + 0];
                const float v1 = d[mf][j][half * 2 + 1];
                uint32_t hi, lo;
                split_pair(v0, v1, hi, lo);
                if (mat == 0) {
                    *(uint32_t*)&g_qh[row * 64 + h] = hi;
                    *(uint32_t*)&g_ql[row * 64 + h] = lo;
                } else if (mat == 1) {
                    *(uint32_t*)&g_kh[row * 64 + h] = hi;
                    *(uint32_t*)&g_kl[row * 64 + h] = lo;
                } else {
                    const int b = row >> 11, t = row & 2047;
                    __nv_bfloat16 h0 = __float2bfloat16(v0);
                    __nv_bfloat16 h1 = __float2bfloat16(v1);
                    g_vth[b][h][t]     = h0;
                    g_vth[b][h + 1][t] = h1;
                    g_vtl[b][h][t]     = __float2bfloat16(v0 - __bfloat162float(h0));
                    g_vtl[b][h + 1][t] = __float2bfloat16(v1 - __bfloat162float(h1));
                }
            }
        }
    }
}

// ---------------------------------------------------------------------------
// FA2-style split-KV flash attention (R8, kept). BQ=64, 128 threads, 4 warps.
// ---------------------------------------------------------------------------
#define SCALE_L2E 0.18033688f   // 64^-0.5 * log2(e)
#define STAGE_BYTES 36864
#define ARR_BYTES   9216        // 64*72*2

__global__ __launch_bounds__(128, 3) void attn_kernel()
{
    const int qt = (QTILES - 1) - blockIdx.x;   // longest-first
    const int ntile = qt + 1;
    const int sp = blockIdx.z;
    const int t0 = sp * TILES_PER_SPLIT;
    if (t0 >= ntile) return;
    const int t1 = min(t0 + TILES_PER_SPLIT, ntile);

    extern __shared__ __align__(16) char smbuf[];
    const uint32_t smbase = (uint32_t)__cvta_generic_to_shared(smbuf);

    const int tid  = threadIdx.x;
    const int lane = tid & 31;
    const int warp = tid >> 5;
    const int lq = lane >> 2;
    const int lc = (lane & 3) * 2;

    const int b  = blockIdx.y;
    const int q_base = qt * 64;
    const int boff = b * T_SEQ * 64;
    const __nv_bfloat16* qbh = g_qh + boff;
    const __nv_bfloat16* qbl = g_ql + boff;
    const __nv_bfloat16* kbh = g_kh + boff;
    const __nv_bfloat16* kbl = g_kl + boff;

    {
        __nv_bfloat16* Qh = (__nv_bfloat16*)(smbuf);
        __nv_bfloat16* Ql = (__nv_bfloat16*)(smbuf + ARR_BYTES);
        #pragma unroll
        for (int p = 0; p < 4; p++) {
            const int idx = tid + p * 128;
            const int r = idx >> 3, u = idx & 7;
            *(uint4*)&Qh[r * 72 + u * 8] =
                *(const uint4*)&qbh[(q_base + r) * 64 + u * 8];
            *(uint4*)&Ql[r * 72 + u * 8] =
                *(const uint4*)&qbl[(q_base + r) * 64 + u * 8];
        }
    }
    __syncthreads();
    uint32_t qa_h[4][4], qa_l[4][4];
    {
        const __nv_bfloat16* Qh = (const __nv_bfloat16*)(smbuf);
        const __nv_bfloat16* Ql = (const __nv_bfloat16*)(smbuf + ARR_BYTES);
        const int rb = warp * 16;
        #pragma unroll
        for (int kc = 0; kc < 4; kc++) {
            const int cb = kc * 16 + lc;
            qa_h[kc][0] = *(const uint32_t*)&Qh[(rb + lq) * 72 + cb];
            qa_h[kc][1] = *(const uint32_t*)&Qh[(rb + lq + 8) * 72 + cb];
            qa_h[kc][2] = *(const uint32_t*)&Qh[(rb + lq) * 72 + cb + 8];
            qa_h[kc][3] = *(const uint32_t*)&Qh[(rb + lq + 8) * 72 + cb + 8];
            qa_l[kc][0] = *(const uint32_t*)&Ql[(rb + lq) * 72 + cb];
            qa_l[kc][1] = *(const uint32_t*)&Ql[(rb + lq + 8) * 72 + cb];
            qa_l[kc][2] = *(const uint32_t*)&Ql[(rb + lq) * 72 + cb + 8];
            qa_l[kc][3] = *(const uint32_t*)&Ql[(rb + lq + 8) * 72 + cb + 8];
        }
    }
    __syncthreads();

    #define PREFETCH(stage, kb_)                                                 \
    do {                                                                         \
        const uint32_t stoff = smbase + (stage) * STAGE_BYTES;                   \
        _Pragma("unroll")                                                        \
        for (int p = 0; p < 4; p++) {                                            \
            const int idx = tid + p * 128;                                       \
            const int r = idx >> 3, u = idx & 7;                                 \
            const uint32_t o = stoff + r * 144 + u * 16;                         \
            CP_ASYNC16(o,                  &kbh[((kb_) + r) * 64 + u * 8]);      \
            CP_ASYNC16(o + ARR_BYTES,      &kbl[((kb_) + r) * 64 + u * 8]);      \
            CP_ASYNC16(o + 2 * ARR_BYTES,  &g_vth[b][r][(kb_) + u * 8]);         \
            CP_ASYNC16(o + 3 * ARR_BYTES,  &g_vtl[b][r][(kb_) + u * 8]);         \
        }                                                                        \
    } while (0)

    PREFETCH(0, t0 * 64);
    CP_COMMIT();

    float of[8][4];
    #pragma unroll
    for (int j = 0; j < 8; j++)
        #pragma unroll
        for (int r = 0; r < 4; r++) of[j][r] = 0.0f;
    float m2[2] = {-1e30f, -1e30f};
    float lsum[2] = {0.0f, 0.0f};

    int buf = 0;
    for (int t = t0; t < t1; t++) {
        const int kb = t * 64;
        const bool more = (t + 1 < t1);
        if (more) { PREFETCH(buf ^ 1, (t + 1) * 64); CP_COMMIT(); }
        if (more) CP_WAIT1(); else CP_WAIT0();
        __syncthreads();

        const __nv_bfloat16* Kh = (const __nv_bfloat16*)(smbuf + buf * STAGE_BYTES);
        const __nv_bfloat16* Kl = Kh + ARR_BYTES / 2;
        const __nv_bfloat16* Vh = Kh + ARR_BYTES;
        const __nv_bfloat16* Vl = Kh + 3 * ARR_BYTES / 2;

        float s[8][4];
        #pragma unroll
        for (int j = 0; j < 8; j++)
            #pragma unroll
            for (int r = 0; r < 4; r++) s[j][r] = 0.0f;
        #pragma unroll
        for (int kc = 0; kc < 4; kc++) {
            const int cb = kc * 16 + lc;
            #pragma unroll
            for (int j = 0; j < 8; j++) {
                const int sr = j * 8 + lq;
                uint32_t bh[2], bl[2];
                bh[0] = *(const uint32_t*)&Kh[sr * 72 + cb];
                bh[1] = *(const uint32_t*)&Kh[sr * 72 + cb + 8];
                bl[0] = *(const uint32_t*)&Kl[sr * 72 + cb];
                bl[1] = *(const uint32_t*)&Kl[sr * 72 + cb + 8];
                mma_bf16(s[j], qa_h[kc], bh);
                mma_bf16(s[j], qa_h[kc], bl);
                mma_bf16(s[j], qa_l[kc], bh);
            }
        }

        if (t == qt) {
            #pragma unroll
            for (int j = 0; j < 8; j++) {
                const int col = kb + j * 8 + lc;
                #pragma unroll
                for (int half = 0; half < 2; half++) {
                    const int qrow = q_base + warp * 16 + lq + half * 8;
                    s[j][half * 2 + 0] = (col     <= qrow) ? s[j][half * 2 + 0] * SCALE_L2E : -1e30f;
                    s[j][half * 2 + 1] = (col + 1 <= qrow) ? s[j][half * 2 + 1] * SCALE_L2E : -1e30f;
                }
            }
        } else {
            #pragma unroll
            for (int j = 0; j < 8; j++)
                #pragma unroll
                for (int r = 0; r < 4; r++) s[j][r] *= SCALE_L2E;
        }

        float pm[2] = {-1e30f, -1e30f};
        #pragma unroll
        for (int j = 0; j < 8; j++) {
            pm[0] = fmaxf(pm[0], fmaxf(s[j][0], s[j][1]));
            pm[1] = fmaxf(pm[1], fmaxf(s[j][2], s[j][3]));
        }
        pm[0] = fmaxf(pm[0], __shfl_xor_sync(0xffffffffu, pm[0], 1));
        pm[1] = fmaxf(pm[1], __shfl_xor_sync(0xffffffffu, pm[1], 1));
        pm[0] = fmaxf(pm[0], __shfl_xor_sync(0xffffffffu, pm[0], 2));
        pm[1] = fmaxf(pm[1], __shfl_xor_sync(0xffffffffu, pm[1], 2));

        float mnew[2], alpha[2];
        #pragma unroll
        for (int half = 0; half < 2; half++) {
            mnew[half]  = fmaxf(m2[half], pm[half]);
            alpha[half] = exp2_poly(m2[half] - mnew[half]);
            m2[half]    = mnew[half];
        }
        float ps[2] = {0.0f, 0.0f};
        #pragma unroll
        for (int j = 0; j < 8; j++) {
            s[j][0] = exp2_poly(s[j][0] - mnew[0]);
            s[j][1] = exp2_poly(s[j][1] - mnew[0]);
            s[j][2] = exp2_poly(s[j][2] - mnew[1]);
            s[j][3] = exp2_poly(s[j][3] - mnew[1]);
            ps[0] += s[j][0] + s[j][1];
            ps[1] += s[j][2] + s[j][3];
        }
        ps[0] += __shfl_xor_sync(0xffffffffu, ps[0], 1);
        ps[1] += __shfl_xor_sync(0xffffffffu, ps[1], 1);
        ps[0] += __shfl_xor_sync(0xffffffffu, ps[0], 2);
        ps[1] += __shfl_xor_sync(0xffffffffu, ps[1], 2);

        lsum[0] = lsum[0] * alpha[0] + ps[0];
        lsum[1] = lsum[1] * alpha[1] + ps[1];
        #pragma unroll
        for (int j = 0; j < 8; j++) {
            of[j][0] *= alpha[0]; of[j][1] *= alpha[0];
            of[j][2] *= alpha[1]; of[j][3] *= alpha[1];
        }

        #pragma unroll
        for (int kc = 0; kc < 4; kc++) {
            const int cb = kc * 16 + lc;
            uint32_t ap_h[4], ap_l[4];
            split_pair(s[2 * kc][0],     s[2 * kc][1],     ap_h[0], ap_l[0]);
            split_pair(s[2 * kc][2],     s[2 * kc][3],     ap_h[1], ap_l[1]);
            split_pair(s[2 * kc + 1][0], s[2 * kc + 1][1], ap_h[2], ap_l[2]);
            split_pair(s[2 * kc + 1][2], s[2 * kc + 1][3], ap_h[3], ap_l[3]);
            #pragma unroll
            for (int j = 0; j < 8; j++) {
                const int hr = j * 8 + lq;
                uint32_t bh[2], bl[2];
                bh[0] = *(const uint32_t*)&Vh[hr * 72 + cb];
                bh[1] = *(const uint32_t*)&Vh[hr * 72 + cb + 8];
                bl[0] = *(const uint32_t*)&Vl[hr * 72 + cb];
                bl[1] = *(const uint32_t*)&Vl[hr * 72 + cb + 8];
                mma_bf16(of[j], ap_h, bh);
                mma_bf16(of[j], ap_h, bl);
                mma_bf16(of[j], ap_l, bh);
            }
        }
        __syncthreads();
        buf ^= 1;
    }

    const int rowg = b * T_SEQ + q_base + warp * 16 + lq;
    #pragma unroll
    for (int j = 0; j < 8; j++) {
        const int col = j * 8 + lc;
        *(float2*)&g_po[sp][rowg][col]     = make_float2(of[j][0], of[j][1]);
        *(float2*)&g_po[sp][rowg + 8][col] = make_float2(of[j][2], of[j][3]);
    }
    if ((lane & 3) == 0) {
        g_pm[sp][rowg]     = m2[0];
        g_pm[sp][rowg + 8] = m2[1];
        g_pl[sp][rowg]     = lsum[0];
        g_pl[sp][rowg + 8] = lsum[1];
    }
}

// ---------------------------------------------------------------------------
// Combine partial splits, float4 per thread, batched split loads. (R9, kept)
// ---------------------------------------------------------------------------
__global__ __launch_bounds__(128) void combine_kernel(float* __restrict__ out)
{
    const int idx = blockIdx.x * 128 + threadIdx.x;
    const int r = idx >> 4;
    const int c = (idx & 15) * 4;
    const int rr = r & (T_SEQ - 1);
    const int qt = rr >> 6;
    const int nsplit = ((qt + 1) + TILES_PER_SPLIT - 1) / TILES_PER_SPLIT;

    float pm[NSPLIT];
    float M = -1e30f;
    #pragma unroll
    for (int s = 0; s < NSPLIT; s++) {
        pm[s] = (s < nsplit) ? g_pm[s][r] : -1e30f;
        M = fmaxf(M, pm[s]);
    }
    float L = 0.0f;
    float4 acc = make_float4(0.0f, 0.0f, 0.0f, 0.0f);
    #pragma unroll
    for (int s = 0; s < NSPLIT; s++) {
        if (s < nsplit) {
            const float w = exp2_poly(pm[s] - M);
            L += w * g_pl[s][r];
            float4 o = *(const float4*)&g_po[s][r][c];
            acc.x += w * o.x; acc.y += w * o.y;
            acc.z += w * o.z; acc.w += w * o.w;
        }
    }
    const float inv = 1.0f / L;
    acc.x *= inv; acc.y *= inv; acc.z *= inv; acc.w *= inv;
    *(float4*)&out[r * 64 + c] = acc;
}

extern "C" void kernel_launch(void* const* d_in, const int* in_sizes, int n_in,
                              void* d_out, int out_size)
{
    const float* x  = (const float*)d_in[0];
    const float* Wq = (const float*)d_in[1];
    const float* Wk = (const float*)d_in[2];
    const float* Wv = (const float*)d_in[3];
    float* out = (float*)d_out;

    cudaFuncSetAttribute(attn_kernel,
                         cudaFuncAttributeMaxDynamicSharedMemorySize,
                         2 * STAGE_BYTES);
    cudaFuncSetAttribute(qkv_mma_kernel,
                         cudaFuncAttributeMaxDynamicSharedMemorySize,
                         2 * QS_STAGE);

    split_w_kernel<<<3 * 64 * 1024 / 256, 256>>>(Wq, Wk, Wv);
    qkv_mma_kernel<<<M_TOT / 64, 256, 2 * QS_STAGE>>>(x);
    attn_kernel<<<dim3(QTILES, B_SZ, NSPLIT), 128, 2 * STAGE_BYTES>>>();
    combine_kernel<<<M_TOT * H_SZ / 512, 128>>>(out);
}

// round 11
// speedup vs baseline: 1.9519x; 1.2062x over previous
#include <cuda_runtime.h>
#include <cuda_bf16.h>
#include <cuda_fp16.h>
#include <cstdint>

#define D_IN 1024
#define H_SZ 64
#define M_TOT 8192   // B*T
#define T_SEQ 2048
#define B_SZ 4
#define NSPLIT 4
#define TILES_PER_SPLIT 8
#define QTILES 32            // T_SEQ / 64

// ---------------- global scratch ----------------
__device__ __nv_bfloat16 g_wh[192 * D_IN];     // [w*64+n][k]  (W transposed)
__device__ __nv_bfloat16 g_wl[192 * D_IN];
__device__ __nv_bfloat16 g_qh[M_TOT * H_SZ];   // [global token][h], PRE-SCALED
__device__ __nv_bfloat16 g_ql[M_TOT * H_SZ];
__device__ __nv_bfloat16 g_kh[M_TOT * H_SZ];
__device__ __nv_bfloat16 g_kl[M_TOT * H_SZ];
__device__ __half        g_vt[B_SZ][H_SZ][T_SEQ];   // V transposed, single fp16
// split-KV partials
__device__ float g_po[NSPLIT][M_TOT][H_SZ];    // unnormalized O
__device__ float g_pm[NSPLIT][M_TOT];          // running max (log2 domain)
__device__ float g_pl[NSPLIT][M_TOT];          // running sum

// ---------------- helpers ----------------
__device__ __forceinline__ void mma_bf16(float d[4], const uint32_t a[4],
                                         const uint32_t b[2]) {
    asm("mma.sync.aligned.m16n8k16.row.col.f32.bf16.bf16.f32 "
        "{%0,%1,%2,%3}, {%4,%5,%6,%7}, {%8,%9}, {%0,%1,%2,%3};\n"
        : "+f"(d[0]), "+f"(d[1]), "+f"(d[2]), "+f"(d[3])
        : "r"(a[0]), "r"(a[1]), "r"(a[2]), "r"(a[3]), "r"(b[0]), "r"(b[1]));
}

__device__ __forceinline__ void mma_fp16(float d[4], const uint32_t a[4],
                                         const uint32_t b[2]) {
    asm("mma.sync.aligned.m16n8k16.row.col.f32.f16.f16.f32 "
        "{%0,%1,%2,%3}, {%4,%5,%6,%7}, {%8,%9}, {%0,%1,%2,%3};\n"
        : "+f"(d[0]), "+f"(d[1]), "+f"(d[2]), "+f"(d[3])
        : "r"(a[0]), "r"(a[1]), "r"(a[2]), "r"(a[3]), "r"(b[0]), "r"(b[1]));
}

__device__ __forceinline__ uint32_t pack2bf(float v0, float v1) {
    unsigned short l = __bfloat16_as_ushort(__float2bfloat16(v0));
    unsigned short h = __bfloat16_as_ushort(__float2bfloat16(v1));
    return (uint32_t)l | ((uint32_t)h << 16);
}

__device__ __forceinline__ void split_pair(float x, float y,
                                           uint32_t& hi, uint32_t& lo) {
    __nv_bfloat16 hx = __float2bfloat16(x);
    __nv_bfloat16 hy = __float2bfloat16(y);
    hi = (uint32_t)__bfloat16_as_ushort(hx) |
         ((uint32_t)__bfloat16_as_ushort(hy) << 16);
    lo = pack2bf(x - __bfloat162float(hx), y - __bfloat162float(hy));
}

__device__ __forceinline__ uint32_t pack2h(float v0, float v1) {
    __half2 h = __floats2half2_rn(v0, v1);
    return *(uint32_t*)&h;
}

// hardware exp2 (MUFU): ~2 ulp, -1e30 underflows to 0 (ftz).
__device__ __forceinline__ float ex2f(float x) {
    float r;
    asm("ex2.approx.ftz.f32 %0, %1;" : "=f"(r) : "f"(x));
    return r;
}

#define CP_ASYNC16(dst, src) \
    asm volatile("cp.async.cg.shared.global [%0], [%1], 16;" \
                 :: "r"(dst), "l"(src) : "memory")
#define CP_COMMIT() asm volatile("cp.async.commit_group;" ::: "memory")
#define CP_WAIT1()  asm volatile("cp.async.wait_group 1;" ::: "memory")
#define CP_WAIT0()  asm volatile("cp.async.wait_group 0;" ::: "memory")

#define SCALE_L2E 0.18033688f   // 64^-0.5 * log2(e)

// ---------------------------------------------------------------------------
// transpose + split W: [k][n] fp32 -> [w*64+n][k] bf16 hi/lo
// ---------------------------------------------------------------------------
__global__ __launch_bounds__(256) void split_w_kernel(
    const float* __restrict__ Wq, const float* __restrict__ Wk,
    const float* __restrict__ Wv)
{
    const int idx = blockIdx.x * 256 + threadIdx.x;
    const int w = idx >> 16;
    const int n = (idx >> 10) & 63;
    const int k = idx & 1023;
    const float* W = (w == 0) ? Wq : ((w == 1) ? Wk : Wv);
    const float val = W[k * 64 + n];
    __nv_bfloat16 h = __float2bfloat16(val);
    g_wh[idx] = h;
    g_wl[idx] = __float2bfloat16(val - __bfloat162float(h));
}

// ---------------------------------------------------------------------------
// QKV projection (R10 pipeline, kept). Epilogue changes:
//   q pre-scaled by SCALE_L2E before hi/lo split; v stored single fp16.
// ---------------------------------------------------------------------------
#define QS_XL    5120
#define QS_WH    10240
#define QS_WL    25600
#define QS_STAGE 40960

__global__ __launch_bounds__(256) void qkv_mma_kernel(const float* __restrict__ x)
{
    extern __shared__ __align__(16) char qsm[];
    const uint32_t smbase = (uint32_t)__cvta_generic_to_shared(qsm);

    const int tid  = threadIdx.x;
    const int lane = tid & 31;
    const int wid  = tid >> 5;
    const int wm = wid & 1, wn = wid >> 1;
    const int lq = lane >> 2;
    const int lc = (lane & 3) * 2;
    const int m0 = blockIdx.x * 64;

    const int xr0 = tid >> 3;
    const int xr1 = xr0 + 32;
    const int xu  = tid & 7;

    #define QPREF_W(stage, c_)                                                 \
    do {                                                                       \
        const uint32_t st = smbase + (stage) * QS_STAGE;                       \
        const int k0 = (c_) * 32;                                              \
        _Pragma("unroll")                                                      \
        for (int p = 0; p < 3; p++) {                                          \
            const int idx = tid + p * 256;                                     \
            const int r = idx >> 2, u = idx & 3;                               \
            CP_ASYNC16(st + QS_WH + r * 80 + u * 16,                           \
                       &g_wh[r * D_IN + k0 + u * 8]);                          \
            CP_ASYNC16(st + QS_WL + r * 80 + u * 16,                           \
                       &g_wl[r * D_IN + k0 + u * 8]);                          \
        }                                                                      \
    } while (0)

    float d[2][6][4];
    #pragma unroll
    for (int mf = 0; mf < 2; mf++)
        #pragma unroll
        for (int j = 0; j < 6; j++)
            #pragma unroll
            for (int r = 0; r < 4; r++) d[mf][j][r] = 0.0f;

    float4 xr[2];
    xr[0] = *(const float4*)&x[(m0 + xr0) * D_IN + xu * 4];
    xr[1] = *(const float4*)&x[(m0 + xr1) * D_IN + xu * 4];
    QPREF_W(0, 0);
    CP_COMMIT();

    for (int c = 0; c < 32; c++) {
        const int buf = c & 1;
        char* st = qsm + buf * QS_STAGE;
        __nv_bfloat16* xs_h = (__nv_bfloat16*)st;
        __nv_bfloat16* xs_l = (__nv_bfloat16*)(st + QS_XL);
        const __nv_bfloat16* wsh = (const __nv_bfloat16*)(st + QS_WH);
        const __nv_bfloat16* wsl = (const __nv_bfloat16*)(st + QS_WL);

        #pragma unroll
        for (int p = 0; p < 2; p++) {
            const int r = (p == 0) ? xr0 : xr1;
            uint32_t hi01, lo01, hi23, lo23;
            split_pair(xr[p].x, xr[p].y, hi01, lo01);
            split_pair(xr[p].z, xr[p].w, hi23, lo23);
            *(uint2*)&xs_h[r * 40 + xu * 4] = make_uint2(hi01, hi23);
            *(uint2*)&xs_l[r * 40 + xu * 4] = make_uint2(lo01, lo23);
        }
        if (c + 1 < 32) {
            const int k0n = (c + 1) * 32;
            xr[0] = *(const float4*)&x[(m0 + xr0) * D_IN + k0n + xu * 4];
            xr[1] = *(const float4*)&x[(m0 + xr1) * D_IN + k0n + xu * 4];
        }
        CP_WAIT0();
        __syncthreads();
        if (c + 1 < 32) { QPREF_W(buf ^ 1, c + 1); CP_COMMIT(); }

        #pragma unroll
        for (int kc = 0; kc < 2; kc++) {
            const int cb = kc * 16 + lc;
            uint32_t ah[2][4], al[2][4];
            #pragma unroll
            for (int mf = 0; mf < 2; mf++) {
                const int rb = wm * 32 + mf * 16;
                ah[mf][0] = *(const uint32_t*)&xs_h[(rb + lq) * 40 + cb];
                ah[mf][1] = *(const uint32_t*)&xs_h[(rb + lq + 8) * 40 + cb];
                ah[mf][2] = *(const uint32_t*)&xs_h[(rb + lq) * 40 + cb + 8];
                ah[mf][3] = *(const uint32_t*)&xs_h[(rb + lq + 8) * 40 + cb + 8];
                al[mf][0] = *(const uint32_t*)&xs_l[(rb + lq) * 40 + cb];
                al[mf][1] = *(const uint32_t*)&xs_l[(rb + lq + 8) * 40 + cb];
                al[mf][2] = *(const uint32_t*)&xs_l[(rb + lq) * 40 + cb + 8];
                al[mf][3] = *(const uint32_t*)&xs_l[(rb + lq + 8) * 40 + cb + 8];
            }
            #pragma unroll
            for (int j = 0; j < 6; j++) {
                const int wr = wn * 48 + j * 8 + lq;
                uint32_t bh[2], bl[2];
                bh[0] = *(const uint32_t*)&wsh[wr * 40 + cb];
                bh[1] = *(const uint32_t*)&wsh[wr * 40 + cb + 8];
                bl[0] = *(const uint32_t*)&wsl[wr * 40 + cb];
                bl[1] = *(const uint32_t*)&wsl[wr * 40 + cb + 8];
                #pragma unroll
                for (int mf = 0; mf < 2; mf++) {
                    mma_bf16(d[mf][j], ah[mf], bh);
                    mma_bf16(d[mf][j], ah[mf], bl);
                    mma_bf16(d[mf][j], al[mf], bh);
                }
            }
        }
        __syncthreads();
    }

    // epilogue
    #pragma unroll
    for (int mf = 0; mf < 2; mf++) {
        #pragma unroll
        for (int j = 0; j < 6; j++) {
            const int col = wn * 48 + j * 8 + lc;
            const int mat = col >> 6;
            const int h   = col & 63;
            #pragma unroll
            for (int half = 0; half < 2; half++) {
                const int row = m0 + wm * 32 + mf * 16 + lq + half * 8;
                float v0 = d[mf][j][half * 2 + 0];
                float v1 = d[mf][j][half * 2 + 1];
                if (mat == 0) {
                    v0 *= SCALE_L2E; v1 *= SCALE_L2E;   // pre-scale q
                    uint32_t hi, lo;
                    split_pair(v0, v1, hi, lo);
                    *(uint32_t*)&g_qh[row * 64 + h] = hi;
                    *(uint32_t*)&g_ql[row * 64 + h] = lo;
                } else if (mat == 1) {
                    uint32_t hi, lo;
                    split_pair(v0, v1, hi, lo);
                    *(uint32_t*)&g_kh[row * 64 + h] = hi;
                    *(uint32_t*)&g_kl[row * 64 + h] = lo;
                } else {
                    const int b = row >> 11, t = row & 2047;
                    g_vt[b][h][t]     = __float2half(v0);
                    g_vt[b][h + 1][t] = __float2half(v1);
                }
            }
        }
    }
}

// ---------------------------------------------------------------------------
// FA2-style split-KV flash attention. BQ=64, 128 threads, 4 warps.
// GEMM1: 3-term bf16 (q pre-scaled). Softmax: MUFU ex2. GEMM2: SINGLE fp16
// product (P fp16 regs x V fp16). Stage = Kh|Kl|Vh = 27648 B, 2 stages.
// ---------------------------------------------------------------------------
#define STAGE_BYTES 27648
#define ARR_BYTES   9216        // 64*72*2

__global__ __launch_bounds__(128, 3) void attn_kernel()
{
    const int qt = (QTILES - 1) - blockIdx.x;   // longest-first
    const int ntile = qt + 1;
    const int sp = blockIdx.z;
    const int t0 = sp * TILES_PER_SPLIT;
    if (t0 >= ntile) return;
    const int t1 = min(t0 + TILES_PER_SPLIT, ntile);

    extern __shared__ __align__(16) char smbuf[];
    const uint32_t smbase = (uint32_t)__cvta_generic_to_shared(smbuf);

    const int tid  = threadIdx.x;
    const int lane = tid & 31;
    const int warp = tid >> 5;
    const int lq = lane >> 2;
    const int lc = (lane & 3) * 2;

    const int b  = blockIdx.y;
    const int q_base = qt * 64;
    const int boff = b * T_SEQ * 64;
    const __nv_bfloat16* qbh = g_qh + boff;
    const __nv_bfloat16* qbl = g_ql + boff;
    const __nv_bfloat16* kbh = g_kh + boff;
    const __nv_bfloat16* kbl = g_kl + boff;

    // Q tile via stage-0 smem, extract frags, release
    {
        __nv_bfloat16* Qh = (__nv_bfloat16*)(smbuf);
        __nv_bfloat16* Ql = (__nv_bfloat16*)(smbuf + ARR_BYTES);
        #pragma unroll
        for (int p = 0; p < 4; p++) {
            const int idx = tid + p * 128;
            const int r = idx >> 3, u = idx & 7;
            *(uint4*)&Qh[r * 72 + u * 8] =
                *(const uint4*)&qbh[(q_base + r) * 64 + u * 8];
            *(uint4*)&Ql[r * 72 + u * 8] =
                *(const uint4*)&qbl[(q_base + r) * 64 + u * 8];
        }
    }
    __syncthreads();
    uint32_t qa_h[4][4], qa_l[4][4];
    {
        const __nv_bfloat16* Qh = (const __nv_bfloat16*)(smbuf);
        const __nv_bfloat16* Ql = (const __nv_bfloat16*)(smbuf + ARR_BYTES);
        const int rb = warp * 16;
        #pragma unroll
        for (int kc = 0; kc < 4; kc++) {
            const int cb = kc * 16 + lc;
            qa_h[kc][0] = *(const uint32_t*)&Qh[(rb + lq) * 72 + cb];
            qa_h[kc][1] = *(const uint32_t*)&Qh[(rb + lq + 8) * 72 + cb];
            qa_h[kc][2] = *(const uint32_t*)&Qh[(rb + lq) * 72 + cb + 8];
            qa_h[kc][3] = *(const uint32_t*)&Qh[(rb + lq + 8) * 72 + cb + 8];
            qa_l[kc][0] = *(const uint32_t*)&Ql[(rb + lq) * 72 + cb];
            qa_l[kc][1] = *(const uint32_t*)&Ql[(rb + lq + 8) * 72 + cb];
            qa_l[kc][2] = *(const uint32_t*)&Ql[(rb + lq) * 72 + cb + 8];
            qa_l[kc][3] = *(const uint32_t*)&Ql[(rb + lq + 8) * 72 + cb + 8];
        }
    }
    __syncthreads();

    #define PREFETCH(stage, kb_)                                                 \
    do {                                                                         \
        const uint32_t stoff = smbase + (stage) * STAGE_BYTES;                   \
        _Pragma("unroll")                                                        \
        for (int p = 0; p < 4; p++) {                                            \
            const int idx = tid + p * 128;                                       \
            const int r = idx >> 3, u = idx & 7;                                 \
            const uint32_t o = stoff + r * 144 + u * 16;                         \
            CP_ASYNC16(o,                  &kbh[((kb_) + r) * 64 + u * 8]);      \
            CP_ASYNC16(o + ARR_BYTES,      &kbl[((kb_) + r) * 64 + u * 8]);      \
            CP_ASYNC16(o + 2 * ARR_BYTES,  &g_vt[b][r][(kb_) + u * 8]);          \
        }                                                                        \
    } while (0)

    PREFETCH(0, t0 * 64);
    CP_COMMIT();

    float of[8][4];
    #pragma unroll
    for (int j = 0; j < 8; j++)
        #pragma unroll
        for (int r = 0; r < 4; r++) of[j][r] = 0.0f;
    float m2[2] = {-1e30f, -1e30f};
    float lsum[2] = {0.0f, 0.0f};

    int buf = 0;
    for (int t = t0; t < t1; t++) {
        const int kb = t * 64;
        const bool more = (t + 1 < t1);
        if (more) { PREFETCH(buf ^ 1, (t + 1) * 64); CP_COMMIT(); }
        if (more) CP_WAIT1(); else CP_WAIT0();
        __syncthreads();

        const __nv_bfloat16* Kh = (const __nv_bfloat16*)(smbuf + buf * STAGE_BYTES);
        const __nv_bfloat16* Kl = Kh + ARR_BYTES / 2;
        const __half* Vh = (const __half*)((const char*)Kh + 2 * ARR_BYTES);

        // GEMM1: S = Q K^T (3-term bf16; q pre-scaled by SCALE_L2E)
        float s[8][4];
        #pragma unroll
        for (int j = 0; j < 8; j++)
            #pragma unroll
            for (int r = 0; r < 4; r++) s[j][r] = 0.0f;
        #pragma unroll
        for (int kc = 0; kc < 4; kc++) {
            const int cb = kc * 16 + lc;
            #pragma unroll
            for (int j = 0; j < 8; j++) {
                const int sr = j * 8 + lq;
                uint32_t bh[2], bl[2];
                bh[0] = *(const uint32_t*)&Kh[sr * 72 + cb];
                bh[1] = *(const uint32_t*)&Kh[sr * 72 + cb + 8];
                bl[0] = *(const uint32_t*)&Kl[sr * 72 + cb];
                bl[1] = *(const uint32_t*)&Kl[sr * 72 + cb + 8];
                mma_bf16(s[j], qa_h[kc], bh);
                mma_bf16(s[j], qa_h[kc], bl);
                mma_bf16(s[j], qa_l[kc], bh);
            }
        }

        // causal mask (diagonal tile only; scale already folded into q)
        if (t == qt) {
            #pragma unroll
            for (int j = 0; j < 8; j++) {
                const int col = kb + j * 8 + lc;
                #pragma unroll
                for (int half = 0; half < 2; half++) {
                    const int qrow = q_base + warp * 16 + lq + half * 8;
                    s[j][half * 2 + 0] = (col     <= qrow) ? s[j][half * 2 + 0] : -1e30f;
                    s[j][half * 2 + 1] = (col + 1 <= qrow) ? s[j][half * 2 + 1] : -1e30f;
                }
            }
        }

        // row stats in-warp (quad shuffles)
        float pm[2] = {-1e30f, -1e30f};
        #pragma unroll
        for (int j = 0; j < 8; j++) {
            pm[0] = fmaxf(pm[0], fmaxf(s[j][0], s[j][1]));
            pm[1] = fmaxf(pm[1], fmaxf(s[j][2], s[j][3]));
        }
        pm[0] = fmaxf(pm[0], __shfl_xor_sync(0xffffffffu, pm[0], 1));
        pm[1] = fmaxf(pm[1], __shfl_xor_sync(0xffffffffu, pm[1], 1));
        pm[0] = fmaxf(pm[0], __shfl_xor_sync(0xffffffffu, pm[0], 2));
        pm[1] = fmaxf(pm[1], __shfl_xor_sync(0xffffffffu, pm[1], 2));

        float mnew[2], alpha[2];
        #pragma unroll
        for (int half = 0; half < 2; half++) {
            mnew[half]  = fmaxf(m2[half], pm[half]);
            alpha[half] = ex2f(m2[half] - mnew[half]);
            m2[half]    = mnew[half];
        }
        float ps[2] = {0.0f, 0.0f};
        #pragma unroll
        for (int j = 0; j < 8; j++) {
            s[j][0] = ex2f(s[j][0] - mnew[0]);
            s[j][1] = ex2f(s[j][1] - mnew[0]);
            s[j][2] = ex2f(s[j][2] - mnew[1]);
            s[j][3] = ex2f(s[j][3] - mnew[1]);
            ps[0] += s[j][0] + s[j][1];
            ps[1] += s[j][2] + s[j][3];
        }
        ps[0] += __shfl_xor_sync(0xffffffffu, ps[0], 1);
        ps[1] += __shfl_xor_sync(0xffffffffu, ps[1], 1);
        ps[0] += __shfl_xor_sync(0xffffffffu, ps[0], 2);
        ps[1] += __shfl_xor_sync(0xffffffffu, ps[1], 2);

        lsum[0] = lsum[0] * alpha[0] + ps[0];
        lsum[1] = lsum[1] * alpha[1] + ps[1];
        #pragma unroll
        for (int j = 0; j < 8; j++) {
            of[j][0] *= alpha[0]; of[j][1] *= alpha[0];
            of[j][2] *= alpha[1]; of[j][3] *= alpha[1];
        }

        // GEMM2: O += P V — SINGLE fp16 product (P packed in regs)
        #pragma unroll
        for (int kc = 0; kc < 4; kc++) {
            const int cb = kc * 16 + lc;
            uint32_t ap[4];
            ap[0] = pack2h(s[2 * kc][0],     s[2 * kc][1]);
            ap[1] = pack2h(s[2 * kc][2],     s[2 * kc][3]);
            ap[2] = pack2h(s[2 * kc + 1][0], s[2 * kc + 1][1]);
            ap[3] = pack2h(s[2 * kc + 1][2], s[2 * kc + 1][3]);
            #pragma unroll
            for (int j = 0; j < 8; j++) {
                const int hr = j * 8 + lq;
                uint32_t bh[2];
                bh[0] = *(const uint32_t*)&Vh[hr * 72 + cb];
                bh[1] = *(const uint32_t*)&Vh[hr * 72 + cb + 8];
                mma_fp16(of[j], ap, bh);
            }
        }
        __syncthreads();
        buf ^= 1;
    }

    const int rowg = b * T_SEQ + q_base + warp * 16 + lq;
    #pragma unroll
    for (int j = 0; j < 8; j++) {
        const int col = j * 8 + lc;
        *(float2*)&g_po[sp][rowg][col]     = make_float2(of[j][0], of[j][1]);
        *(float2*)&g_po[sp][rowg + 8][col] = make_float2(of[j][2], of[j][3]);
    }
    if ((lane & 3) == 0) {
        g_pm[sp][rowg]     = m2[0];
        g_pm[sp][rowg + 8] = m2[1];
        g_pl[sp][rowg]     = lsum[0];
        g_pl[sp][rowg + 8] = lsum[1];
    }
}

// ---------------------------------------------------------------------------
// Combine partial splits (R9/R10, ex2 hardware).
// ---------------------------------------------------------------------------
__global__ __launch_bounds__(128) void combine_kernel(float* __restrict__ out)
{
    const int idx = blockIdx.x * 128 + threadIdx.x;
    const int r = idx >> 4;
    const int c = (idx & 15) * 4;
    const int rr = r & (T_SEQ - 1);
    const int qt = rr >> 6;
    const int nsplit = ((qt + 1) + TILES_PER_SPLIT - 1) / TILES_PER_SPLIT;

    float pm[NSPLIT];
    float M = -1e30f;
    #pragma unroll
    for (int s = 0; s < NSPLIT; s++) {
        pm[s] = (s < nsplit) ? g_pm[s][r] : -1e30f;
        M = fmaxf(M, pm[s]);
    }
    float L = 0.0f;
    float4 acc = make_float4(0.0f, 0.0f, 0.0f, 0.0f);
    #pragma unroll
    for (int s = 0; s < NSPLIT; s++) {
        if (s < nsplit) {
            const float w = ex2f(pm[s] - M);
            L += w * g_pl[s][r];
            float4 o = *(const float4*)&g_po[s][r][c];
            acc.x += w * o.x; acc.y += w * o.y;
            acc.z += w * o.z; acc.w += w * o.w;
        }
    }
    const float inv = 1.0f / L;
    acc.x *= inv; acc.y *= inv; acc.z *= inv; acc.w *= inv;
    *(float4*)&out[r * 64 + c] = acc;
}

extern "C" void kernel_launch(void* const* d_in, const int* in_sizes, int n_in,
                              void* d_out, int out_size)
{
    const float* x  = (const float*)d_in[0];
    const float* Wq = (const float*)d_in[1];
    const float* Wk = (const float*)d_in[2];
    const float* Wv = (const float*)d_in[3];
    float* out = (float*)d_out;

    cudaFuncSetAttribute(attn_kernel,
                         cudaFuncAttributeMaxDynamicSharedMemorySize,
                         2 * STAGE_BYTES);
    cudaFuncSetAttribute(qkv_mma_kernel,
                         cudaFuncAttributeMaxDynamicSharedMemorySize,
                         2 * QS_STAGE);

    split_w_kernel<<<3 * 64 * 1024 / 256, 256>>>(Wq, Wk, Wv);
    qkv_mma_kernel<<<M_TOT / 64, 256, 2 * QS_STAGE>>>(x);
    attn_kernel<<<dim3(QTILES, B_SZ, NSPLIT), 128, 2 * STAGE_BYTES>>>();
    combine_kernel<<<M_TOT * H_SZ / 512, 128>>>(out);
}